// round 1
// baseline (speedup 1.0000x reference)
#include <cuda_runtime.h>
#include <cuda_bf16.h>
#include <math.h>

// Problem constants
#define B_  4
#define S_  2048
#define E_  1024
#define H_  16
#define HD_ 64
#define N3E (3 * E_)          // 3072
#define MROWS (B_ * S_)       // 8192
#define O_ELEMS ((size_t)MROWS * E_)            // 8388608
#define ATTN_ELEMS ((size_t)B_ * H_ * S_ * S_)  // 268435456

// Scratch (allowed: __device__ global arrays)
__device__ float g_qkv[(size_t)MROWS * N3E];   // [B,S,3E]  ~100.7 MB
__device__ float g_vals[(size_t)MROWS * E_];   // [B,S,E]   ~33.5 MB

// ----------------------------------------------------------------------------
// Generic tiled GEMM with bias: C[M,N] = A[M,K] @ W[K,N] + bias[N]
// 64x64 tile, K-tile 16, 256 threads, 4x4 per thread.
// M,N,K all multiples of 64/16 in this problem: no bounds checks.
// ----------------------------------------------------------------------------
__global__ void gemm_bias_kernel(const float* __restrict__ A,
                                 const float* __restrict__ W,
                                 const float* __restrict__ bias,
                                 float* __restrict__ C,
                                 int M, int N, int K) {
    __shared__ float As[16][64];   // [k][m]
    __shared__ float Ws[16][64];   // [k][n]
    const int tid = threadIdx.x;
    const int tx = tid & 15;
    const int ty = tid >> 4;
    const int m0 = blockIdx.y * 64;
    const int n0 = blockIdx.x * 64;

    // A tile loader: thread -> row m0 + tid/4, k-offset (tid%4)*4 (one float4)
    const int la_m = tid >> 2;
    const int la_k = (tid & 3) * 4;
    // W tile loader: thread -> k row tid/16, n-offset (tid%16)*4 (one float4)
    const int lw_k = tid >> 4;
    const int lw_n = (tid & 15) * 4;

    float acc[4][4] = {};
    for (int k0 = 0; k0 < K; k0 += 16) {
        float4 av = *(const float4*)&A[(size_t)(m0 + la_m) * K + k0 + la_k];
        As[la_k + 0][la_m] = av.x;
        As[la_k + 1][la_m] = av.y;
        As[la_k + 2][la_m] = av.z;
        As[la_k + 3][la_m] = av.w;
        float4 wv = *(const float4*)&W[(size_t)(k0 + lw_k) * N + n0 + lw_n];
        *(float4*)&Ws[lw_k][lw_n] = wv;
        __syncthreads();
        #pragma unroll
        for (int kk = 0; kk < 16; kk++) {
            float a[4], bv[4];
            #pragma unroll
            for (int i = 0; i < 4; i++) a[i] = As[kk][ty * 4 + i];
            #pragma unroll
            for (int j = 0; j < 4; j++) bv[j] = Ws[kk][tx * 4 + j];
            #pragma unroll
            for (int i = 0; i < 4; i++)
                #pragma unroll
                for (int j = 0; j < 4; j++)
                    acc[i][j] += a[i] * bv[j];
        }
        __syncthreads();
    }
    #pragma unroll
    for (int i = 0; i < 4; i++) {
        const int m = m0 + ty * 4 + i;
        #pragma unroll
        for (int j = 0; j < 4; j++) {
            const int n = n0 + tx * 4 + j;
            C[(size_t)m * N + n] = acc[i][j] + bias[n];
        }
    }
}

// ----------------------------------------------------------------------------
// Logits: for each (b,h), L[i,j] = (Q_i . K_j) / 8, lower triangle only.
// Q[b,h,s,d] = qkv[(b*S+s)*3E + h*192 + d]; K at +64. 64x64 tiles.
// Upper-triangle tiles skipped entirely (softmax writes zeros there).
// ----------------------------------------------------------------------------
__global__ void logits_kernel(float* __restrict__ attn) {
    const int ki = blockIdx.x;
    const int qi = blockIdx.y;
    if (ki > qi) return;
    const int bh = blockIdx.z;
    const int b = bh >> 4;
    const int h = bh & 15;
    const float* base = g_qkv + (size_t)b * S_ * N3E + h * (3 * HD_);

    __shared__ float Qs[64][65];   // [d][i]
    __shared__ float Ks[64][65];   // [d][j]
    const int tid = threadIdx.x;
    const int lrow = tid >> 2;          // 0..63
    const int ld0 = (tid & 3) * 16;     // 0,16,32,48

    const float* qrow = base + (size_t)(qi * 64 + lrow) * N3E + ld0;
    const float* krow = base + (size_t)(ki * 64 + lrow) * N3E + HD_ + ld0;
    #pragma unroll
    for (int dd = 0; dd < 16; dd += 4) {
        float4 qv = *(const float4*)(qrow + dd);
        Qs[ld0 + dd + 0][lrow] = qv.x;
        Qs[ld0 + dd + 1][lrow] = qv.y;
        Qs[ld0 + dd + 2][lrow] = qv.z;
        Qs[ld0 + dd + 3][lrow] = qv.w;
        float4 kv = *(const float4*)(krow + dd);
        Ks[ld0 + dd + 0][lrow] = kv.x;
        Ks[ld0 + dd + 1][lrow] = kv.y;
        Ks[ld0 + dd + 2][lrow] = kv.z;
        Ks[ld0 + dd + 3][lrow] = kv.w;
    }
    __syncthreads();

    const int tx = tid & 15;
    const int ty = tid >> 4;
    float acc[4][4] = {};
    #pragma unroll 8
    for (int d = 0; d < 64; d++) {
        float a[4], bv[4];
        #pragma unroll
        for (int i = 0; i < 4; i++) a[i] = Qs[d][ty * 4 + i];
        #pragma unroll
        for (int j = 0; j < 4; j++) bv[j] = Ks[d][tx * 4 + j];
        #pragma unroll
        for (int i = 0; i < 4; i++)
            #pragma unroll
            for (int j = 0; j < 4; j++)
                acc[i][j] += a[i] * bv[j];
    }

    const float scale = 0.125f;  // 1/sqrt(64)
    const size_t rowbase = (size_t)bh * S_;
    #pragma unroll
    for (int i = 0; i < 4; i++) {
        const int ig = qi * 64 + ty * 4 + i;
        #pragma unroll
        for (int j = 0; j < 4; j++) {
            const int jg = ki * 64 + tx * 4 + j;
            float v = acc[i][j] * scale;
            if (jg > ig) v = -9e15f;   // diagonal tile masking (never read anyway)
            attn[(rowbase + ig) * S_ + jg] = v;
        }
    }
}

// ----------------------------------------------------------------------------
// Row softmax over [B*H*S, S] with causal valid length L = (row % S) + 1.
// Writes exp-normalized values for j < L and exact 0 for j >= L.
// One block (256 threads) per row; 8 values per thread held in registers.
// ----------------------------------------------------------------------------
__inline__ __device__ float warpMax(float v) {
    #pragma unroll
    for (int o = 16; o > 0; o >>= 1) v = fmaxf(v, __shfl_xor_sync(0xffffffffu, v, o));
    return v;
}
__inline__ __device__ float warpSum(float v) {
    #pragma unroll
    for (int o = 16; o > 0; o >>= 1) v += __shfl_xor_sync(0xffffffffu, v, o);
    return v;
}

__global__ void softmax_kernel(float* __restrict__ attn) {
    const int row = blockIdx.x;             // bh*S + i
    const int L = (row & (S_ - 1)) + 1;     // causal length
    float* p = attn + (size_t)row * S_;
    const int tid = threadIdx.x;

    float vals[8];
    float mx = -3.4e38f;
    #pragma unroll
    for (int r = 0; r < 8; r++) {
        const int j = tid + r * 256;
        vals[r] = (j < L) ? p[j] : -3.4e38f;
        mx = fmaxf(mx, vals[r]);
    }

    __shared__ float red[8];
    float wm = warpMax(mx);
    if ((tid & 31) == 0) red[tid >> 5] = wm;
    __syncthreads();
    float bm = red[tid & 7];
    bm = warpMax(bm);   // all 8 partials live in each warp's first 8 lanes pattern; redo properly:
    // simpler correct block max:
    __syncthreads();
    if (tid < 8) red[tid] = red[tid];
    __syncthreads();
    float m0 = red[0];
    #pragma unroll
    for (int r = 1; r < 8; r++) m0 = fmaxf(m0, red[r]);

    float s = 0.f;
    #pragma unroll
    for (int r = 0; r < 8; r++) {
        const int j = tid + r * 256;
        float e = (j < L) ? __expf(vals[r] - m0) : 0.f;
        vals[r] = e;
        s += e;
    }
    __shared__ float reds[8];
    float ws = warpSum(s);
    if ((tid & 31) == 0) reds[tid >> 5] = ws;
    __syncthreads();
    float tot = reds[0];
    #pragma unroll
    for (int r = 1; r < 8; r++) tot += reds[r];
    const float inv = __frcp_rn(tot);

    #pragma unroll
    for (int r = 0; r < 8; r++) {
        const int j = tid + r * 256;
        p[j] = vals[r] * inv;   // zeros beyond L are exact (vals[r]==0)
    }
}

// ----------------------------------------------------------------------------
// A·V: per (b,h), out[i,d] = sum_k attn[i,k] * V[k,d], k tiles up to diagonal.
// Writes vals in [B,S,E] layout: g_vals[(b*S+i)*E + h*64 + d].
// ----------------------------------------------------------------------------
__global__ void av_kernel(const float* __restrict__ attn) {
    const int qi = blockIdx.y;
    const int bh = blockIdx.z;
    const int b = bh >> 4;
    const int h = bh & 15;
    const float* vbase = g_qkv + (size_t)b * S_ * N3E + h * (3 * HD_) + 2 * HD_;
    const float* arow0 = attn + ((size_t)bh * S_ + qi * 64) * S_;

    __shared__ float Ats[64][65];  // [k][i]
    __shared__ float Vs[64][64];   // [k][d]
    const int tid = threadIdx.x;
    const int lrow = tid >> 2;
    const int lc0 = (tid & 3) * 16;
    const int tx = tid & 15;
    const int ty = tid >> 4;

    float acc[4][4] = {};
    for (int kt = 0; kt <= qi; kt++) {
        const float* ar = arow0 + (size_t)lrow * S_ + kt * 64 + lc0;
        #pragma unroll
        for (int dd = 0; dd < 16; dd += 4) {
            float4 av = *(const float4*)(ar + dd);
            Ats[lc0 + dd + 0][lrow] = av.x;
            Ats[lc0 + dd + 1][lrow] = av.y;
            Ats[lc0 + dd + 2][lrow] = av.z;
            Ats[lc0 + dd + 3][lrow] = av.w;
        }
        const float* vr = vbase + (size_t)(kt * 64 + lrow) * N3E + lc0;
        #pragma unroll
        for (int dd = 0; dd < 16; dd += 4) {
            *(float4*)&Vs[lrow][lc0 + dd] = *(const float4*)(vr + dd);
        }
        __syncthreads();
        #pragma unroll 8
        for (int kk = 0; kk < 64; kk++) {
            float a[4], bv[4];
            #pragma unroll
            for (int i = 0; i < 4; i++) a[i] = Ats[kk][ty * 4 + i];
            #pragma unroll
            for (int j = 0; j < 4; j++) bv[j] = Vs[kk][tx * 4 + j];
            #pragma unroll
            for (int i = 0; i < 4; i++)
                #pragma unroll
                for (int j = 0; j < 4; j++)
                    acc[i][j] += a[i] * bv[j];
        }
        __syncthreads();
    }
    #pragma unroll
    for (int i = 0; i < 4; i++) {
        const int s = qi * 64 + ty * 4 + i;
        #pragma unroll
        for (int j = 0; j < 4; j++) {
            const int d = tx * 4 + j;
            g_vals[((size_t)b * S_ + s) * E_ + h * HD_ + d] = acc[i][j];
        }
    }
}

// ----------------------------------------------------------------------------
extern "C" void kernel_launch(void* const* d_in, const int* in_sizes, int n_in,
                              void* d_out, int out_size) {
    const float* x     = (const float*)d_in[0];
    const float* w_qkv = (const float*)d_in[1];
    const float* b_qkv = (const float*)d_in[2];
    const float* w_o   = (const float*)d_in[3];
    const float* b_o   = (const float*)d_in[4];
    // d_in[5] = mask (causal, known analytically) — unused

    float* out  = (float*)d_out;
    float* attn = out + O_ELEMS;

    float* qkv_ptr = nullptr;
    float* vals_ptr = nullptr;
    cudaGetSymbolAddress((void**)&qkv_ptr, g_qkv);
    cudaGetSymbolAddress((void**)&vals_ptr, g_vals);

    // 1) QKV projection: [8192,1024] @ [1024,3072] + b
    gemm_bias_kernel<<<dim3(N3E / 64, MROWS / 64), 256>>>(
        x, w_qkv, b_qkv, qkv_ptr, MROWS, N3E, E_);

    // 2) causal logits into attn region
    logits_kernel<<<dim3(S_ / 64, S_ / 64, B_ * H_), 256>>>(attn);

    // 3) row softmax (writes full rows: probs + exact zeros)
    softmax_kernel<<<B_ * H_ * S_, 256>>>(attn);

    // 4) A @ V -> vals [B,S,E]
    av_kernel<<<dim3(1, S_ / 64, B_ * H_), 256>>>(attn);

    // 5) output projection: [8192,1024] @ [1024,1024] + b_o
    gemm_bias_kernel<<<dim3(E_ / 64, MROWS / 64), 256>>>(
        vals_ptr, w_o, b_o, out, MROWS, E_, E_);
}

// round 2
// speedup vs baseline: 2.6816x; 2.6816x over previous
#include <cuda_runtime.h>
#include <stdint.h>
#include <math.h>

// Problem constants
#define B_  4
#define S_  2048
#define E_  1024
#define H_  16
#define HD_ 64
#define N3E 3072
#define MROWS 8192
#define O_ELEMS ((size_t)MROWS * E_)            // 8388608

// Scratch (__device__ globals: allowed)
__device__ float g_qkv[(size_t)MROWS * N3E];    // [B,S,3E]
__device__ float g_vals[(size_t)MROWS * E_];    // [B,S,E]
__device__ float g_rowsum[64 * S_];             // per (bh,row) exp-sum

// ---------------------------------------------------------------------------
// tf32 helpers
// ---------------------------------------------------------------------------
__device__ __forceinline__ uint32_t f2tf(float f) {
    uint32_t u;
    asm("cvt.rna.tf32.f32 %0, %1;" : "=r"(u) : "f"(f));
    return u;
}

__device__ __forceinline__ void mma_tf32(float c[4],
                                         uint32_t a0, uint32_t a1, uint32_t a2, uint32_t a3,
                                         uint32_t b0, uint32_t b1) {
    asm volatile(
        "mma.sync.aligned.m16n8k8.row.col.f32.tf32.tf32.f32 "
        "{%0,%1,%2,%3}, {%4,%5,%6,%7}, {%8,%9}, {%0,%1,%2,%3};"
        : "+f"(c[0]), "+f"(c[1]), "+f"(c[2]), "+f"(c[3])
        : "r"(a0), "r"(a1), "r"(a2), "r"(a3), "r"(b0), "r"(b1));
}

// ---------------------------------------------------------------------------
// K1/K5: GEMM C[M,N] = A[M,K] @ W[K,N] + bias[N], tf32 tensor cores.
// Block tile 128x128, K-tile 32, 256 threads (8 warps as 2m x 4n, warp 64x32).
// ---------------------------------------------------------------------------
__global__ void gemm_tf32_kernel(const float* __restrict__ A,
                                 const float* __restrict__ W,
                                 const float* __restrict__ bias,
                                 float* __restrict__ C,
                                 int M, int N, int K) {
    __shared__ uint32_t As[128][36];   // [m][k], pad 4 -> conflict-free frag reads
    __shared__ uint32_t Bs[32][136];   // [k][n], pad 8
    const int tid = threadIdx.x;
    const int warp = tid >> 5, lane = tid & 31;
    const int g = lane >> 2, t = lane & 3;
    const int m0 = blockIdx.y * 128, n0 = blockIdx.x * 128;
    const int wm = (warp >> 2) * 64;
    const int wn = (warp & 3) * 32;

    float acc[4][4][4] = {};

    for (int k0 = 0; k0 < K; k0 += 32) {
        #pragma unroll
        for (int i = 0; i < 4; i++) {
            int idx = tid + i * 256;
            int r = idx >> 3, c4 = (idx & 7) << 2;
            float4 v = *(const float4*)&A[(size_t)(m0 + r) * K + k0 + c4];
            As[r][c4 + 0] = f2tf(v.x); As[r][c4 + 1] = f2tf(v.y);
            As[r][c4 + 2] = f2tf(v.z); As[r][c4 + 3] = f2tf(v.w);
        }
        #pragma unroll
        for (int i = 0; i < 4; i++) {
            int idx = tid + i * 256;
            int r = idx >> 5, c4 = (idx & 31) << 2;
            float4 v = *(const float4*)&W[(size_t)(k0 + r) * N + n0 + c4];
            Bs[r][c4 + 0] = f2tf(v.x); Bs[r][c4 + 1] = f2tf(v.y);
            Bs[r][c4 + 2] = f2tf(v.z); Bs[r][c4 + 3] = f2tf(v.w);
        }
        __syncthreads();
        #pragma unroll
        for (int kk = 0; kk < 32; kk += 8) {
            uint32_t a[4][4], b[4][2];
            #pragma unroll
            for (int mi = 0; mi < 4; mi++) {
                int r = wm + mi * 16 + g;
                a[mi][0] = As[r][kk + t];
                a[mi][1] = As[r + 8][kk + t];
                a[mi][2] = As[r][kk + t + 4];
                a[mi][3] = As[r + 8][kk + t + 4];
            }
            #pragma unroll
            for (int ni = 0; ni < 4; ni++) {
                int c = wn + ni * 8 + g;
                b[ni][0] = Bs[kk + t][c];
                b[ni][1] = Bs[kk + t + 4][c];
            }
            #pragma unroll
            for (int mi = 0; mi < 4; mi++)
                #pragma unroll
                for (int ni = 0; ni < 4; ni++)
                    mma_tf32(acc[mi][ni], a[mi][0], a[mi][1], a[mi][2], a[mi][3],
                             b[ni][0], b[ni][1]);
        }
        __syncthreads();
    }

    #pragma unroll
    for (int mi = 0; mi < 4; mi++) {
        int r0 = m0 + wm + mi * 16 + g;
        #pragma unroll
        for (int ni = 0; ni < 4; ni++) {
            int c = n0 + wn + ni * 8 + 2 * t;
            float b0v = bias[c], b1v = bias[c + 1];
            *(float2*)&C[(size_t)r0 * N + c] =
                make_float2(acc[mi][ni][0] + b0v, acc[mi][ni][1] + b1v);
            *(float2*)&C[(size_t)(r0 + 8) * N + c] =
                make_float2(acc[mi][ni][2] + b0v, acc[mi][ni][3] + b1v);
        }
    }
}

// ---------------------------------------------------------------------------
// K2: E = exp(Q·K^T / 8) (causal), write unnormalized E to attn, accumulate
// per-row sums into g_rowsum. 128x128 tile per block, lower-triangular only.
// Dynamic smem: Qs[128][68] + Ks[128][68] (uint32 tf32) = 69632 B.
// ---------------------------------------------------------------------------
__global__ void logits_exp_kernel(float* __restrict__ attn) {
    const int kt = blockIdx.x, qt = blockIdx.y, bh = blockIdx.z;
    if (kt > qt) return;
    const int b = bh >> 4, h = bh & 15;

    extern __shared__ uint32_t sm2[];
    uint32_t (*Qs)[68] = (uint32_t(*)[68])sm2;
    uint32_t (*Ks)[68] = (uint32_t(*)[68])(sm2 + 128 * 68);
    __shared__ float srow[128];

    const int tid = threadIdx.x;
    const int warp = tid >> 5, lane = tid & 31;
    const int g = lane >> 2, t = lane & 3;
    const int wm = (warp >> 2) * 64;
    const int wn = (warp & 3) * 32;

    // load Q (qt tile) and K (kt tile): [128 tokens][64 d] each
    #pragma unroll
    for (int i = 0; i < 8; i++) {
        int idx = tid + i * 256;
        int r = idx >> 4, c4 = (idx & 15) << 2;
        float4 q = *(const float4*)&g_qkv[((size_t)b * S_ + qt * 128 + r) * N3E + h * 192 + c4];
        Qs[r][c4 + 0] = f2tf(q.x); Qs[r][c4 + 1] = f2tf(q.y);
        Qs[r][c4 + 2] = f2tf(q.z); Qs[r][c4 + 3] = f2tf(q.w);
        float4 k = *(const float4*)&g_qkv[((size_t)b * S_ + kt * 128 + r) * N3E + h * 192 + 64 + c4];
        Ks[r][c4 + 0] = f2tf(k.x); Ks[r][c4 + 1] = f2tf(k.y);
        Ks[r][c4 + 2] = f2tf(k.z); Ks[r][c4 + 3] = f2tf(k.w);
    }
    if (tid < 128) srow[tid] = 0.f;
    __syncthreads();

    float acc[4][4][4] = {};
    #pragma unroll
    for (int kk = 0; kk < 64; kk += 8) {
        uint32_t a[4][4], bf[4][2];
        #pragma unroll
        for (int mi = 0; mi < 4; mi++) {
            int r = wm + mi * 16 + g;
            a[mi][0] = Qs[r][kk + t];
            a[mi][1] = Qs[r + 8][kk + t];
            a[mi][2] = Qs[r][kk + t + 4];
            a[mi][3] = Qs[r + 8][kk + t + 4];
        }
        #pragma unroll
        for (int ni = 0; ni < 4; ni++) {
            int c = wn + ni * 8 + g;
            bf[ni][0] = Ks[c][kk + t];
            bf[ni][1] = Ks[c][kk + t + 4];
        }
        #pragma unroll
        for (int mi = 0; mi < 4; mi++)
            #pragma unroll
            for (int ni = 0; ni < 4; ni++)
                mma_tf32(acc[mi][ni], a[mi][0], a[mi][1], a[mi][2], a[mi][3],
                         bf[ni][0], bf[ni][1]);
    }

    float sL[4] = {0.f, 0.f, 0.f, 0.f}, sH[4] = {0.f, 0.f, 0.f, 0.f};
    #pragma unroll
    for (int mi = 0; mi < 4; mi++) {
        int gr = qt * 128 + wm + mi * 16 + g;
        #pragma unroll
        for (int ni = 0; ni < 4; ni++) {
            int gc = kt * 128 + wn + ni * 8 + 2 * t;
            float e0 = __expf(acc[mi][ni][0] * 0.125f);
            float e1 = __expf(acc[mi][ni][1] * 0.125f);
            float e2 = __expf(acc[mi][ni][2] * 0.125f);
            float e3 = __expf(acc[mi][ni][3] * 0.125f);
            if (gc > gr)         e0 = 0.f;
            if (gc + 1 > gr)     e1 = 0.f;
            if (gc > gr + 8)     e2 = 0.f;
            if (gc + 1 > gr + 8) e3 = 0.f;
            *(float2*)&attn[((size_t)bh * S_ + gr) * S_ + gc]     = make_float2(e0, e1);
            *(float2*)&attn[((size_t)bh * S_ + gr + 8) * S_ + gc] = make_float2(e2, e3);
            sL[mi] += e0 + e1;
            sH[mi] += e2 + e3;
        }
    }
    #pragma unroll
    for (int mi = 0; mi < 4; mi++) {
        float a = sL[mi], c = sH[mi];
        a += __shfl_xor_sync(0xffffffffu, a, 1);
        a += __shfl_xor_sync(0xffffffffu, a, 2);
        c += __shfl_xor_sync(0xffffffffu, c, 1);
        c += __shfl_xor_sync(0xffffffffu, c, 2);
        if (t == 0) {
            atomicAdd(&srow[wm + mi * 16 + g], a);
            atomicAdd(&srow[wm + mi * 16 + 8 + g], c);
        }
    }
    __syncthreads();
    if (tid < 128)
        atomicAdd(&g_rowsum[(size_t)bh * S_ + qt * 128 + tid], srow[tid]);
}

// ---------------------------------------------------------------------------
// K3: normalize attn in place (writes zeros for strictly-upper tiles) and
// compute A·V on tensor cores, scaled by 1/rowsum at the end.
// Block = (bh, qtile of 128 rows); loops kt over 64-wide column tiles.
// Dynamic smem: Es[128][68] + Vs[64][72] = 53248 B.
// ---------------------------------------------------------------------------
__global__ void norm_av_kernel(float* __restrict__ attn) {
    const int qi = blockIdx.x;
    const int bh = blockIdx.y;
    const int b = bh >> 4, h = bh & 15;
    const int q0 = qi * 128;

    extern __shared__ uint32_t sm3[];
    uint32_t (*Es)[68] = (uint32_t(*)[68])sm3;
    uint32_t (*Vs)[72] = (uint32_t(*)[72])(sm3 + 128 * 68);
    __shared__ float invs[128];

    const int tid = threadIdx.x;
    const int warp = tid >> 5, lane = tid & 31;
    const int g = lane >> 2, t = lane & 3;
    const int wm = (warp >> 1) * 32;   // 4 warps in m
    const int wn = (warp & 1) * 32;    // 2 warps in n

    if (tid < 128) invs[tid] = 1.0f / g_rowsum[(size_t)bh * S_ + q0 + tid];
    __syncthreads();

    float acc[2][4][4] = {};

    for (int kt = 0; kt < 32; kt++) {
        const int c0 = kt * 64;
        if (c0 > q0 + 127) {
            // strictly-upper tile: attn = 0
            const float4 z = make_float4(0.f, 0.f, 0.f, 0.f);
            #pragma unroll
            for (int i = 0; i < 8; i++) {
                int idx = tid + i * 256;
                int r = idx >> 4, c4 = (idx & 15) << 2;
                *(float4*)&attn[((size_t)bh * S_ + q0 + r) * S_ + c0 + c4] = z;
            }
            continue;
        }
        // load E tile [128][64]; write back normalized; keep tf32 copy in smem
        #pragma unroll
        for (int i = 0; i < 8; i++) {
            int idx = tid + i * 256;
            int r = idx >> 4, c4 = (idx & 15) << 2;
            float* p = &attn[((size_t)bh * S_ + q0 + r) * S_ + c0 + c4];
            float4 v = *(const float4*)p;
            float iv = invs[r];
            *(float4*)p = make_float4(v.x * iv, v.y * iv, v.z * iv, v.w * iv);
            Es[r][c4 + 0] = f2tf(v.x); Es[r][c4 + 1] = f2tf(v.y);
            Es[r][c4 + 2] = f2tf(v.z); Es[r][c4 + 3] = f2tf(v.w);
        }
        // load V tile [64 tokens][64 d]
        #pragma unroll
        for (int i = 0; i < 4; i++) {
            int idx = tid + i * 256;
            int r = idx >> 4, c4 = (idx & 15) << 2;
            float4 v = *(const float4*)&g_qkv[((size_t)b * S_ + c0 + r) * N3E + h * 192 + 128 + c4];
            Vs[r][c4 + 0] = f2tf(v.x); Vs[r][c4 + 1] = f2tf(v.y);
            Vs[r][c4 + 2] = f2tf(v.z); Vs[r][c4 + 3] = f2tf(v.w);
        }
        __syncthreads();

        #pragma unroll
        for (int kk = 0; kk < 64; kk += 8) {
            uint32_t a[2][4], bf[4][2];
            #pragma unroll
            for (int mi = 0; mi < 2; mi++) {
                int r = wm + mi * 16 + g;
                a[mi][0] = Es[r][kk + t];
                a[mi][1] = Es[r + 8][kk + t];
                a[mi][2] = Es[r][kk + t + 4];
                a[mi][3] = Es[r + 8][kk + t + 4];
            }
            #pragma unroll
            for (int ni = 0; ni < 4; ni++) {
                int c = wn + ni * 8 + g;
                bf[ni][0] = Vs[kk + t][c];
                bf[ni][1] = Vs[kk + t + 4][c];
            }
            #pragma unroll
            for (int mi = 0; mi < 2; mi++)
                #pragma unroll
                for (int ni = 0; ni < 4; ni++)
                    mma_tf32(acc[mi][ni], a[mi][0], a[mi][1], a[mi][2], a[mi][3],
                             bf[ni][0], bf[ni][1]);
        }
        __syncthreads();
    }

    // scale by 1/rowsum, store to g_vals in [B,S,E] layout
    #pragma unroll
    for (int mi = 0; mi < 2; mi++) {
        int r = wm + mi * 16 + g;
        float i0 = invs[r], i1 = invs[r + 8];
        #pragma unroll
        for (int ni = 0; ni < 4; ni++) {
            int d = h * HD_ + wn + ni * 8 + 2 * t;
            size_t o0 = ((size_t)b * S_ + q0 + r) * E_ + d;
            *(float2*)&g_vals[o0] =
                make_float2(acc[mi][ni][0] * i0, acc[mi][ni][1] * i0);
            *(float2*)&g_vals[o0 + (size_t)8 * E_] =
                make_float2(acc[mi][ni][2] * i1, acc[mi][ni][3] * i1);
        }
    }
}

// ---------------------------------------------------------------------------
__global__ void zero_rowsum_kernel() {
    int idx = (blockIdx.x * 256 + threadIdx.x) * 4;
    *(float4*)&g_rowsum[idx] = make_float4(0.f, 0.f, 0.f, 0.f);
}

// ---------------------------------------------------------------------------
extern "C" void kernel_launch(void* const* d_in, const int* in_sizes, int n_in,
                              void* d_out, int out_size) {
    const float* x     = (const float*)d_in[0];
    const float* w_qkv = (const float*)d_in[1];
    const float* b_qkv = (const float*)d_in[2];
    const float* w_o   = (const float*)d_in[3];
    const float* b_o   = (const float*)d_in[4];
    // d_in[5] = mask (causal, known analytically) — unused

    float* out  = (float*)d_out;
    float* attn = out + O_ELEMS;

    float* qkv_ptr = nullptr;
    float* vals_ptr = nullptr;
    cudaGetSymbolAddress((void**)&qkv_ptr, g_qkv);
    cudaGetSymbolAddress((void**)&vals_ptr, g_vals);

    cudaFuncSetAttribute(logits_exp_kernel,
                         cudaFuncAttributeMaxDynamicSharedMemorySize, 69632);
    cudaFuncSetAttribute(norm_av_kernel,
                         cudaFuncAttributeMaxDynamicSharedMemorySize, 53248);

    // 0) zero rowsums
    zero_rowsum_kernel<<<128, 256>>>();

    // 1) QKV projection [8192,1024]@[1024,3072]+b
    gemm_tf32_kernel<<<dim3(N3E / 128, MROWS / 128), 256>>>(
        x, w_qkv, b_qkv, qkv_ptr, MROWS, N3E, E_);

    // 2) causal exp-logits + rowsums
    logits_exp_kernel<<<dim3(16, 16, 64), 256, 69632>>>(attn);

    // 3) normalize attn in place + A·V
    norm_av_kernel<<<dim3(16, 64), 256, 53248>>>(attn);

    // 4) output projection [8192,1024]@[1024,1024]+b_o
    gemm_tf32_kernel<<<dim3(E_ / 128, MROWS / 128), 256>>>(
        vals_ptr, w_o, b_o, out, MROWS, E_, E_);
}

// round 4
// speedup vs baseline: 3.2539x; 1.2134x over previous
#include <cuda_runtime.h>
#include <stdint.h>
#include <math.h>

// Problem constants
#define B_  4
#define S_  2048
#define E_  1024
#define H_  16
#define HD_ 64
#define N3E 3072
#define MROWS 8192
#define O_ELEMS ((size_t)MROWS * E_)            // 8388608

// Scratch (__device__ globals: allowed)
__device__ float g_qkv[(size_t)MROWS * N3E];    // [B,S,3E]
__device__ float g_vals[(size_t)MROWS * E_];    // [B,S,E]
__device__ float g_rowinv[64 * S_];             // per (bh,row) 1/rowsum

// ---------------------------------------------------------------------------
// tf32 helpers
// ---------------------------------------------------------------------------
__device__ __forceinline__ uint32_t f2tf(float f) {
    uint32_t u;
    asm("cvt.rna.tf32.f32 %0, %1;" : "=r"(u) : "f"(f));
    return u;
}

__device__ __forceinline__ void mma_tf32(float c[4],
                                         uint32_t a0, uint32_t a1, uint32_t a2, uint32_t a3,
                                         uint32_t b0, uint32_t b1) {
    asm volatile(
        "mma.sync.aligned.m16n8k8.row.col.f32.tf32.tf32.f32 "
        "{%0,%1,%2,%3}, {%4,%5,%6,%7}, {%8,%9}, {%0,%1,%2,%3};"
        : "+f"(c[0]), "+f"(c[1]), "+f"(c[2]), "+f"(c[3])
        : "r"(a0), "r"(a1), "r"(a2), "r"(a3), "r"(b0), "r"(b1));
}

// ---------------------------------------------------------------------------
// K1/K4: GEMM C[M,N] = A[M,K] @ W[K,N] + bias[N], tf32 tensor cores.
// Block tile 128x128, K-tile 32, 256 threads (8 warps as 2m x 4n, warp 64x32).
// ---------------------------------------------------------------------------
__global__ void gemm_tf32_kernel(const float* __restrict__ A,
                                 const float* __restrict__ W,
                                 const float* __restrict__ bias,
                                 float* __restrict__ C,
                                 int M, int N, int K) {
    __shared__ uint32_t As[128][36];
    __shared__ uint32_t Bs[32][136];
    const int tid = threadIdx.x;
    const int warp = tid >> 5, lane = tid & 31;
    const int g = lane >> 2, t = lane & 3;
    const int m0 = blockIdx.y * 128, n0 = blockIdx.x * 128;
    const int wm = (warp >> 2) * 64;
    const int wn = (warp & 3) * 32;

    float acc[4][4][4] = {};

    for (int k0 = 0; k0 < K; k0 += 32) {
        #pragma unroll
        for (int i = 0; i < 4; i++) {
            int idx = tid + i * 256;
            int r = idx >> 3, c4 = (idx & 7) << 2;
            float4 v = *(const float4*)&A[(size_t)(m0 + r) * K + k0 + c4];
            As[r][c4 + 0] = f2tf(v.x); As[r][c4 + 1] = f2tf(v.y);
            As[r][c4 + 2] = f2tf(v.z); As[r][c4 + 3] = f2tf(v.w);
        }
        #pragma unroll
        for (int i = 0; i < 4; i++) {
            int idx = tid + i * 256;
            int r = idx >> 5, c4 = (idx & 31) << 2;
            float4 v = *(const float4*)&W[(size_t)(k0 + r) * N + n0 + c4];
            Bs[r][c4 + 0] = f2tf(v.x); Bs[r][c4 + 1] = f2tf(v.y);
            Bs[r][c4 + 2] = f2tf(v.z); Bs[r][c4 + 3] = f2tf(v.w);
        }
        __syncthreads();
        #pragma unroll
        for (int kk = 0; kk < 32; kk += 8) {
            uint32_t a[4][4], b[4][2];
            #pragma unroll
            for (int mi = 0; mi < 4; mi++) {
                int r = wm + mi * 16 + g;
                a[mi][0] = As[r][kk + t];
                a[mi][1] = As[r + 8][kk + t];
                a[mi][2] = As[r][kk + t + 4];
                a[mi][3] = As[r + 8][kk + t + 4];
            }
            #pragma unroll
            for (int ni = 0; ni < 4; ni++) {
                int c = wn + ni * 8 + g;
                b[ni][0] = Bs[kk + t][c];
                b[ni][1] = Bs[kk + t + 4][c];
            }
            #pragma unroll
            for (int mi = 0; mi < 4; mi++)
                #pragma unroll
                for (int ni = 0; ni < 4; ni++)
                    mma_tf32(acc[mi][ni], a[mi][0], a[mi][1], a[mi][2], a[mi][3],
                             b[ni][0], b[ni][1]);
        }
        __syncthreads();
    }

    #pragma unroll
    for (int mi = 0; mi < 4; mi++) {
        int r0 = m0 + wm + mi * 16 + g;
        #pragma unroll
        for (int ni = 0; ni < 4; ni++) {
            int c = n0 + wn + ni * 8 + 2 * t;
            float b0v = bias[c], b1v = bias[c + 1];
            *(float2*)&C[(size_t)r0 * N + c] =
                make_float2(acc[mi][ni][0] + b0v, acc[mi][ni][1] + b1v);
            *(float2*)&C[(size_t)(r0 + 8) * N + c] =
                make_float2(acc[mi][ni][2] + b0v, acc[mi][ni][3] + b1v);
        }
    }
}

// ---------------------------------------------------------------------------
// K2: fused flash-style attention. Per (bh, 128-row q tile):
//   loop kt tiles up to diagonal: S = Q K^T, E = exp(S/8) (causal-masked),
//   rowsum accumulated in registers, AV += E V (E routed through smem).
// Writes g_vals (unpermuted heads) and g_rowinv. NO attn writes.
// Dyn smem: Qs/Ks/Vs [128][68] + Es [128][132] = 172032 B.
// ---------------------------------------------------------------------------
__global__ __launch_bounds__(256) void attn_fused_kernel() {
    const int qi = (int)gridDim.x - 1 - (int)blockIdx.x;  // heavy blocks first
    const int bh = blockIdx.y;
    const int b = bh >> 4, h = bh & 15;
    const int q0 = qi * 128;

    extern __shared__ uint32_t sm[];
    uint32_t (*Qs)[68]  = (uint32_t(*)[68])sm;
    uint32_t (*Ks)[68]  = (uint32_t(*)[68])(sm + 128 * 68);
    uint32_t (*Vs)[68]  = (uint32_t(*)[68])(sm + 2 * 128 * 68);
    uint32_t (*Es)[132] = (uint32_t(*)[132])(sm + 3 * 128 * 68);
    __shared__ float srow[128];

    const int tid = threadIdx.x;
    const int warp = tid >> 5, lane = tid & 31;
    const int g = lane >> 2, t = lane & 3;
    const int wm = (warp >> 2) * 64, wn = (warp & 3) * 32;   // S layout 2m x 4n
    const int wm2 = (warp >> 1) * 32, wn2 = (warp & 1) * 32; // AV layout 4m x 2n

    // load Q tile [128][64]
    #pragma unroll
    for (int i = 0; i < 8; i++) {
        int idx = tid + i * 256;
        int r = idx >> 4, c4 = (idx & 15) << 2;
        float4 q = *(const float4*)&g_qkv[((size_t)b * S_ + q0 + r) * N3E + h * 192 + c4];
        Qs[r][c4 + 0] = f2tf(q.x); Qs[r][c4 + 1] = f2tf(q.y);
        Qs[r][c4 + 2] = f2tf(q.z); Qs[r][c4 + 3] = f2tf(q.w);
    }
    if (tid < 128) srow[tid] = 0.f;

    float av[2][4][4] = {};
    float sL[4] = {0.f, 0.f, 0.f, 0.f}, sH[4] = {0.f, 0.f, 0.f, 0.f};

    for (int kt = 0; kt <= qi; kt++) {
        __syncthreads();  // guard reuse of Ks/Vs/Es from previous iteration
        #pragma unroll
        for (int i = 0; i < 8; i++) {
            int idx = tid + i * 256;
            int r = idx >> 4, c4 = (idx & 15) << 2;
            size_t rowoff = ((size_t)b * S_ + kt * 128 + r) * N3E + h * 192;
            float4 k = *(const float4*)&g_qkv[rowoff + 64 + c4];
            Ks[r][c4 + 0] = f2tf(k.x); Ks[r][c4 + 1] = f2tf(k.y);
            Ks[r][c4 + 2] = f2tf(k.z); Ks[r][c4 + 3] = f2tf(k.w);
            float4 v = *(const float4*)&g_qkv[rowoff + 128 + c4];
            Vs[r][c4 + 0] = f2tf(v.x); Vs[r][c4 + 1] = f2tf(v.y);
            Vs[r][c4 + 2] = f2tf(v.z); Vs[r][c4 + 3] = f2tf(v.w);
        }
        __syncthreads();

        // S = Q K^T (128x128x64)
        float acc[4][4][4] = {};
        #pragma unroll
        for (int kk = 0; kk < 64; kk += 8) {
            uint32_t a[4][4], bf[4][2];
            #pragma unroll
            for (int mi = 0; mi < 4; mi++) {
                int r = wm + mi * 16 + g;
                a[mi][0] = Qs[r][kk + t];
                a[mi][1] = Qs[r + 8][kk + t];
                a[mi][2] = Qs[r][kk + t + 4];
                a[mi][3] = Qs[r + 8][kk + t + 4];
            }
            #pragma unroll
            for (int ni = 0; ni < 4; ni++) {
                int c = wn + ni * 8 + g;
                bf[ni][0] = Ks[c][kk + t];
                bf[ni][1] = Ks[c][kk + t + 4];
            }
            #pragma unroll
            for (int mi = 0; mi < 4; mi++)
                #pragma unroll
                for (int ni = 0; ni < 4; ni++)
                    mma_tf32(acc[mi][ni], a[mi][0], a[mi][1], a[mi][2], a[mi][3],
                             bf[ni][0], bf[ni][1]);
        }

        // E = exp(S/8), causal mask on diagonal tile; accumulate row sums
        const bool diag = (kt == qi);
        #pragma unroll
        for (int mi = 0; mi < 4; mi++) {
            int gr = wm + mi * 16 + g;
            #pragma unroll
            for (int ni = 0; ni < 4; ni++) {
                int gc = wn + ni * 8 + 2 * t;
                float e0 = __expf(acc[mi][ni][0] * 0.125f);
                float e1 = __expf(acc[mi][ni][1] * 0.125f);
                float e2 = __expf(acc[mi][ni][2] * 0.125f);
                float e3 = __expf(acc[mi][ni][3] * 0.125f);
                if (diag) {
                    if (gc > gr)         e0 = 0.f;
                    if (gc + 1 > gr)     e1 = 0.f;
                    if (gc > gr + 8)     e2 = 0.f;
                    if (gc + 1 > gr + 8) e3 = 0.f;
                }
                Es[gr][gc] = f2tf(e0);     Es[gr][gc + 1] = f2tf(e1);
                Es[gr + 8][gc] = f2tf(e2); Es[gr + 8][gc + 1] = f2tf(e3);
                sL[mi] += e0 + e1;
                sH[mi] += e2 + e3;
            }
        }
        __syncthreads();

        // AV += E V (128x64x128)
        #pragma unroll
        for (int kk = 0; kk < 128; kk += 8) {
            uint32_t a[2][4], bf[4][2];
            #pragma unroll
            for (int mi = 0; mi < 2; mi++) {
                int r = wm2 + mi * 16 + g;
                a[mi][0] = Es[r][kk + t];
                a[mi][1] = Es[r + 8][kk + t];
                a[mi][2] = Es[r][kk + t + 4];
                a[mi][3] = Es[r + 8][kk + t + 4];
            }
            #pragma unroll
            for (int ni = 0; ni < 4; ni++) {
                int c = wn2 + ni * 8 + g;
                bf[ni][0] = Vs[kk + t][c];
                bf[ni][1] = Vs[kk + t + 4][c];
            }
            #pragma unroll
            for (int mi = 0; mi < 2; mi++)
                #pragma unroll
                for (int ni = 0; ni < 4; ni++)
                    mma_tf32(av[mi][ni], a[mi][0], a[mi][1], a[mi][2], a[mi][3],
                             bf[ni][0], bf[ni][1]);
        }
    }

    // reduce row sums (4 n-warps share rows), publish inverses
    #pragma unroll
    for (int mi = 0; mi < 4; mi++) {
        float a = sL[mi], c = sH[mi];
        a += __shfl_xor_sync(0xffffffffu, a, 1);
        a += __shfl_xor_sync(0xffffffffu, a, 2);
        c += __shfl_xor_sync(0xffffffffu, c, 1);
        c += __shfl_xor_sync(0xffffffffu, c, 2);
        if (t == 0) {
            atomicAdd(&srow[wm + mi * 16 + g], a);
            atomicAdd(&srow[wm + mi * 16 + 8 + g], c);
        }
    }
    __syncthreads();
    if (tid < 128) {
        float inv = 1.0f / srow[tid];
        srow[tid] = inv;
        g_rowinv[(size_t)bh * S_ + q0 + tid] = inv;
    }
    __syncthreads();

    // epilogue: scale by 1/rowsum, write g_vals [B,S,E]
    #pragma unroll
    for (int mi = 0; mi < 2; mi++) {
        int r = wm2 + mi * 16 + g;
        float i0 = srow[r], i1 = srow[r + 8];
        #pragma unroll
        for (int ni = 0; ni < 4; ni++) {
            int d = h * HD_ + wn2 + ni * 8 + 2 * t;
            size_t o0 = ((size_t)b * S_ + q0 + r) * E_ + d;
            *(float2*)&g_vals[o0] =
                make_float2(av[mi][ni][0] * i0, av[mi][ni][1] * i0);
            *(float2*)&g_vals[o0 + (size_t)8 * E_] =
                make_float2(av[mi][ni][2] * i1, av[mi][ni][3] * i1);
        }
    }
}

// ---------------------------------------------------------------------------
// K3: attn writer. Recomputes QK^T per 128x128 tile and writes
// exp(s/8) * rowinv (zeros above diagonal); zero-fills upper tiles.
// attn traffic = exactly the 1.07 GB mandatory write.
// Dyn smem: Qs/Ks [128][68] = 69632 B.
// ---------------------------------------------------------------------------
__global__ __launch_bounds__(256) void attn_write_kernel(float* __restrict__ attn) {
    const int kt = blockIdx.x, qt = blockIdx.y, bh = blockIdx.z;
    const int tid = threadIdx.x;

    if (kt > qt) {  // strictly-upper tile: zeros
        const float4 z = make_float4(0.f, 0.f, 0.f, 0.f);
        #pragma unroll
        for (int i = 0; i < 16; i++) {
            int idx = tid + i * 256;
            int r = idx >> 5, c4 = (idx & 31) << 2;
            *(float4*)&attn[((size_t)bh * S_ + qt * 128 + r) * S_ + kt * 128 + c4] = z;
        }
        return;
    }

    const int b = bh >> 4, h = bh & 15;
    extern __shared__ uint32_t sm2[];
    uint32_t (*Qs)[68] = (uint32_t(*)[68])sm2;
    uint32_t (*Ks)[68] = (uint32_t(*)[68])(sm2 + 128 * 68);
    __shared__ float invs[128];

    const int warp = tid >> 5, lane = tid & 31;
    const int g = lane >> 2, t = lane & 3;
    const int wm = (warp >> 2) * 64, wn = (warp & 3) * 32;

    #pragma unroll
    for (int i = 0; i < 8; i++) {
        int idx = tid + i * 256;
        int r = idx >> 4, c4 = (idx & 15) << 2;
        float4 q = *(const float4*)&g_qkv[((size_t)b * S_ + qt * 128 + r) * N3E + h * 192 + c4];
        Qs[r][c4 + 0] = f2tf(q.x); Qs[r][c4 + 1] = f2tf(q.y);
        Qs[r][c4 + 2] = f2tf(q.z); Qs[r][c4 + 3] = f2tf(q.w);
        float4 k = *(const float4*)&g_qkv[((size_t)b * S_ + kt * 128 + r) * N3E + h * 192 + 64 + c4];
        Ks[r][c4 + 0] = f2tf(k.x); Ks[r][c4 + 1] = f2tf(k.y);
        Ks[r][c4 + 2] = f2tf(k.z); Ks[r][c4 + 3] = f2tf(k.w);
    }
    if (tid < 128) invs[tid] = g_rowinv[(size_t)bh * S_ + qt * 128 + tid];
    __syncthreads();

    float acc[4][4][4] = {};
    #pragma unroll
    for (int kk = 0; kk < 64; kk += 8) {
        uint32_t a[4][4], bf[4][2];
        #pragma unroll
        for (int mi = 0; mi < 4; mi++) {
            int r = wm + mi * 16 + g;
            a[mi][0] = Qs[r][kk + t];
            a[mi][1] = Qs[r + 8][kk + t];
            a[mi][2] = Qs[r][kk + t + 4];
            a[mi][3] = Qs[r + 8][kk + t + 4];
        }
        #pragma unroll
        for (int ni = 0; ni < 4; ni++) {
            int c = wn + ni * 8 + g;
            bf[ni][0] = Ks[c][kk + t];
            bf[ni][1] = Ks[c][kk + t + 4];
        }
        #pragma unroll
        for (int mi = 0; mi < 4; mi++)
            #pragma unroll
            for (int ni = 0; ni < 4; ni++)
                mma_tf32(acc[mi][ni], a[mi][0], a[mi][1], a[mi][2], a[mi][3],
                         bf[ni][0], bf[ni][1]);
    }

    const bool diag = (kt == qt);
    #pragma unroll
    for (int mi = 0; mi < 4; mi++) {
        int lr = wm + mi * 16 + g;
        int gr = qt * 128 + lr;
        float i0 = invs[lr], i1 = invs[lr + 8];
        #pragma unroll
        for (int ni = 0; ni < 4; ni++) {
            int lc = wn + ni * 8 + 2 * t;
            int gc = kt * 128 + lc;
            float e0 = __expf(acc[mi][ni][0] * 0.125f) * i0;
            float e1 = __expf(acc[mi][ni][1] * 0.125f) * i0;
            float e2 = __expf(acc[mi][ni][2] * 0.125f) * i1;
            float e3 = __expf(acc[mi][ni][3] * 0.125f) * i1;
            if (diag) {
                if (lc > lr)         e0 = 0.f;
                if (lc + 1 > lr)     e1 = 0.f;
                if (lc > lr + 8)     e2 = 0.f;
                if (lc + 1 > lr + 8) e3 = 0.f;
            }
            *(float2*)&attn[((size_t)bh * S_ + gr) * S_ + gc]     = make_float2(e0, e1);
            *(float2*)&attn[((size_t)bh * S_ + gr + 8) * S_ + gc] = make_float2(e2, e3);
        }
    }
}

// ---------------------------------------------------------------------------
extern "C" void kernel_launch(void* const* d_in, const int* in_sizes, int n_in,
                              void* d_out, int out_size) {
    const float* x     = (const float*)d_in[0];
    const float* w_qkv = (const float*)d_in[1];
    const float* b_qkv = (const float*)d_in[2];
    const float* w_o   = (const float*)d_in[3];
    const float* b_o   = (const float*)d_in[4];
    // d_in[5] = mask (causal, known analytically) — unused

    float* out  = (float*)d_out;
    float* attn = out + O_ELEMS;

    float* qkv_ptr = nullptr;
    float* vals_ptr = nullptr;
    cudaGetSymbolAddress((void**)&qkv_ptr, g_qkv);
    cudaGetSymbolAddress((void**)&vals_ptr, g_vals);

    cudaFuncSetAttribute(attn_fused_kernel,
                         cudaFuncAttributeMaxDynamicSharedMemorySize, 172032);
    cudaFuncSetAttribute(attn_write_kernel,
                         cudaFuncAttributeMaxDynamicSharedMemorySize, 69632);

    // 1) QKV projection [8192,1024]@[1024,3072]+b
    gemm_tf32_kernel<<<dim3(N3E / 128, MROWS / 128), 256>>>(
        x, w_qkv, b_qkv, qkv_ptr, MROWS, N3E, E_);

    // 2) fused attention: rowinv + A·V (no attn writes)
    attn_fused_kernel<<<dim3(16, 64), 256, 172032>>>();

    // 3) attn writer: normalized probabilities (+ zeros), mandatory 1.07 GB
    attn_write_kernel<<<dim3(16, 16, 64), 256, 69632>>>(attn);

    // 4) output projection [8192,1024]@[1024,1024]+b_o
    gemm_tf32_kernel<<<dim3(E_ / 128, MROWS / 128), 256>>>(
        vals_ptr, w_o, b_o, out, MROWS, E_, E_);
}

// round 6
// speedup vs baseline: 3.3582x; 1.0320x over previous
#include <cuda_runtime.h>
#include <stdint.h>
#include <math.h>

// Problem constants
#define B_  4
#define S_  2048
#define E_  1024
#define H_  16
#define HD_ 64
#define N3E 3072
#define MROWS 8192
#define O_ELEMS ((size_t)MROWS * E_)            // 8388608

// Scratch (__device__ globals: allowed)
__device__ float g_qkv[(size_t)MROWS * N3E];    // [B,S,3E]
__device__ float g_vals[(size_t)MROWS * E_];    // [B,S,E]
__device__ float g_rowinv[64 * S_];             // per (bh,row) 1/rowsum

// ---------------------------------------------------------------------------
// tf32 helpers
// ---------------------------------------------------------------------------
__device__ __forceinline__ uint32_t f2tf(float f) {
    uint32_t u;
    asm("cvt.rna.tf32.f32 %0, %1;" : "=r"(u) : "f"(f));
    return u;
}

__device__ __forceinline__ void mma_tf32(float c[4],
                                         uint32_t a0, uint32_t a1, uint32_t a2, uint32_t a3,
                                         uint32_t b0, uint32_t b1) {
    asm volatile(
        "mma.sync.aligned.m16n8k8.row.col.f32.tf32.tf32.f32 "
        "{%0,%1,%2,%3}, {%4,%5,%6,%7}, {%8,%9}, {%0,%1,%2,%3};"
        : "+f"(c[0]), "+f"(c[1]), "+f"(c[2]), "+f"(c[3])
        : "r"(a0), "r"(a1), "r"(a2), "r"(a3), "r"(b0), "r"(b1));
}

// ---------------------------------------------------------------------------
// K1/K4: GEMM C[M,N] = A[M,K] @ W[K,N] + bias[N], tf32 tensor cores.
// Block tile 128x128, K-tile 32, 256 threads (8 warps 2m x 4n, warp 64x32).
// Software-pipelined: next K-tile prefetched into registers during MMA.
// ---------------------------------------------------------------------------
__global__ void gemm_tf32_kernel(const float* __restrict__ A,
                                 const float* __restrict__ W,
                                 const float* __restrict__ bias,
                                 float* __restrict__ C,
                                 int M, int N, int K) {
    __shared__ uint32_t As[128][36];
    __shared__ uint32_t Bs[32][136];
    const int tid = threadIdx.x;
    const int warp = tid >> 5, lane = tid & 31;
    const int g = lane >> 2, t = lane & 3;
    const int m0 = blockIdx.y * 128, n0 = blockIdx.x * 128;
    const int wm = (warp >> 2) * 64;
    const int wn = (warp & 3) * 32;

    // loader coords (fixed per thread)
    const int ra = tid >> 3, ca = (tid & 7) << 2;    // A: [r][c..c+3], r-stride 32 per chunk? no: idx layout below
    const int rb = tid >> 5, cb = (tid & 31) << 2;   // B

    float4 aPre[4], bPre[4];
    #pragma unroll
    for (int i = 0; i < 4; i++) {
        int idx = tid + i * 256;
        int r = idx >> 3, c4 = (idx & 7) << 2;
        aPre[i] = *(const float4*)&A[(size_t)(m0 + r) * K + c4];
        int r2 = idx >> 5, c42 = (idx & 31) << 2;
        bPre[i] = *(const float4*)&W[(size_t)r2 * N + n0 + c42];
    }
    (void)ra; (void)ca; (void)rb; (void)cb;

    float acc[4][4][4] = {};

    for (int k0 = 0; k0 < K; k0 += 32) {
        // store prefetched tile to smem (convert to tf32)
        #pragma unroll
        for (int i = 0; i < 4; i++) {
            int idx = tid + i * 256;
            int r = idx >> 3, c4 = (idx & 7) << 2;
            As[r][c4 + 0] = f2tf(aPre[i].x); As[r][c4 + 1] = f2tf(aPre[i].y);
            As[r][c4 + 2] = f2tf(aPre[i].z); As[r][c4 + 3] = f2tf(aPre[i].w);
            int r2 = idx >> 5, c42 = (idx & 31) << 2;
            Bs[r2][c42 + 0] = f2tf(bPre[i].x); Bs[r2][c42 + 1] = f2tf(bPre[i].y);
            Bs[r2][c42 + 2] = f2tf(bPre[i].z); Bs[r2][c42 + 3] = f2tf(bPre[i].w);
        }
        __syncthreads();

        // prefetch next tile while MMAs run
        if (k0 + 32 < K) {
            #pragma unroll
            for (int i = 0; i < 4; i++) {
                int idx = tid + i * 256;
                int r = idx >> 3, c4 = (idx & 7) << 2;
                aPre[i] = *(const float4*)&A[(size_t)(m0 + r) * K + k0 + 32 + c4];
                int r2 = idx >> 5, c42 = (idx & 31) << 2;
                bPre[i] = *(const float4*)&W[(size_t)(k0 + 32 + r2) * N + n0 + c42];
            }
        }

        #pragma unroll
        for (int kk = 0; kk < 32; kk += 8) {
            uint32_t a[4][4], b[4][2];
            #pragma unroll
            for (int mi = 0; mi < 4; mi++) {
                int r = wm + mi * 16 + g;
                a[mi][0] = As[r][kk + t];
                a[mi][1] = As[r + 8][kk + t];
                a[mi][2] = As[r][kk + t + 4];
                a[mi][3] = As[r + 8][kk + t + 4];
            }
            #pragma unroll
            for (int ni = 0; ni < 4; ni++) {
                int c = wn + ni * 8 + g;
                b[ni][0] = Bs[kk + t][c];
                b[ni][1] = Bs[kk + t + 4][c];
            }
            #pragma unroll
            for (int mi = 0; mi < 4; mi++)
                #pragma unroll
                for (int ni = 0; ni < 4; ni++)
                    mma_tf32(acc[mi][ni], a[mi][0], a[mi][1], a[mi][2], a[mi][3],
                             b[ni][0], b[ni][1]);
        }
        __syncthreads();
    }

    #pragma unroll
    for (int mi = 0; mi < 4; mi++) {
        int r0 = m0 + wm + mi * 16 + g;
        #pragma unroll
        for (int ni = 0; ni < 4; ni++) {
            int c = n0 + wn + ni * 8 + 2 * t;
            float b0v = bias[c], b1v = bias[c + 1];
            *(float2*)&C[(size_t)r0 * N + c] =
                make_float2(acc[mi][ni][0] + b0v, acc[mi][ni][1] + b1v);
            *(float2*)&C[(size_t)(r0 + 8) * N + c] =
                make_float2(acc[mi][ni][2] + b0v, acc[mi][ni][3] + b1v);
        }
    }
}

// ---------------------------------------------------------------------------
// K2: fused flash-style attention. Per (bh, 128-row q tile):
//   loop kt tiles up to diagonal: S = Q K^T, E = exp(S/8) (causal-masked),
//   rowsum accumulated in registers, AV += E V (E routed through smem).
// K/V tile kt+1 prefetched into registers during S-MMA of tile kt.
// Writes g_vals (unpermuted heads) and g_rowinv. NO attn writes.
// Dyn smem: Qs/Ks/Vs [128][68] + Es [128][132] = 172032 B.
// ---------------------------------------------------------------------------
__global__ __launch_bounds__(256) void attn_fused_kernel() {
    const int qi = (int)gridDim.x - 1 - (int)blockIdx.x;  // heavy blocks first
    const int bh = blockIdx.y;
    const int b = bh >> 4, h = bh & 15;
    const int q0 = qi * 128;

    extern __shared__ uint32_t sm[];
    uint32_t (*Qs)[68]  = (uint32_t(*)[68])sm;
    uint32_t (*Ks)[68]  = (uint32_t(*)[68])(sm + 128 * 68);
    uint32_t (*Vs)[68]  = (uint32_t(*)[68])(sm + 2 * 128 * 68);
    uint32_t (*Es)[132] = (uint32_t(*)[132])(sm + 3 * 128 * 68);
    __shared__ float srow[128];

    const int tid = threadIdx.x;
    const int warp = tid >> 5, lane = tid & 31;
    const int g = lane >> 2, t = lane & 3;
    const int wm = (warp >> 2) * 64, wn = (warp & 3) * 32;   // S layout 2m x 4n
    const int wm2 = (warp >> 1) * 32, wn2 = (warp & 1) * 32; // AV layout 4m x 2n

    // load Q tile [128][64]
    #pragma unroll
    for (int i = 0; i < 8; i++) {
        int idx = tid + i * 256;
        int r = idx >> 4, c4 = (idx & 15) << 2;
        float4 q = *(const float4*)&g_qkv[((size_t)b * S_ + q0 + r) * N3E + h * 192 + c4];
        Qs[r][c4 + 0] = f2tf(q.x); Qs[r][c4 + 1] = f2tf(q.y);
        Qs[r][c4 + 2] = f2tf(q.z); Qs[r][c4 + 3] = f2tf(q.w);
    }
    if (tid < 128) srow[tid] = 0.f;

    // prefetch K/V tile 0 into registers
    float4 kPre[8], vPre[8];
    #pragma unroll
    for (int i = 0; i < 8; i++) {
        int idx = tid + i * 256;
        int r = idx >> 4, c4 = (idx & 15) << 2;
        size_t rowoff = ((size_t)b * S_ + r) * N3E + h * 192;
        kPre[i] = *(const float4*)&g_qkv[rowoff + 64 + c4];
        vPre[i] = *(const float4*)&g_qkv[rowoff + 128 + c4];
    }

    float av[2][4][4] = {};
    float sL[4] = {0.f, 0.f, 0.f, 0.f}, sH[4] = {0.f, 0.f, 0.f, 0.f};

    for (int kt = 0; kt <= qi; kt++) {
        __syncthreads();  // prev AV done reading Vs/Es
        // commit prefetched K/V to smem (convert)
        #pragma unroll
        for (int i = 0; i < 8; i++) {
            int idx = tid + i * 256;
            int r = idx >> 4, c4 = (idx & 15) << 2;
            Ks[r][c4 + 0] = f2tf(kPre[i].x); Ks[r][c4 + 1] = f2tf(kPre[i].y);
            Ks[r][c4 + 2] = f2tf(kPre[i].z); Ks[r][c4 + 3] = f2tf(kPre[i].w);
            Vs[r][c4 + 0] = f2tf(vPre[i].x); Vs[r][c4 + 1] = f2tf(vPre[i].y);
            Vs[r][c4 + 2] = f2tf(vPre[i].z); Vs[r][c4 + 3] = f2tf(vPre[i].w);
        }
        __syncthreads();

        // prefetch next K/V tile while S-MMA runs
        if (kt < qi) {
            #pragma unroll
            for (int i = 0; i < 8; i++) {
                int idx = tid + i * 256;
                int r = idx >> 4, c4 = (idx & 15) << 2;
                size_t rowoff = ((size_t)b * S_ + (kt + 1) * 128 + r) * N3E + h * 192;
                kPre[i] = *(const float4*)&g_qkv[rowoff + 64 + c4];
                vPre[i] = *(const float4*)&g_qkv[rowoff + 128 + c4];
            }
        }

        // S = Q K^T (128x128x64)
        float acc[4][4][4] = {};
        #pragma unroll
        for (int kk = 0; kk < 64; kk += 8) {
            uint32_t a[4][4], bf[4][2];
            #pragma unroll
            for (int mi = 0; mi < 4; mi++) {
                int r = wm + mi * 16 + g;
                a[mi][0] = Qs[r][kk + t];
                a[mi][1] = Qs[r + 8][kk + t];
                a[mi][2] = Qs[r][kk + t + 4];
                a[mi][3] = Qs[r + 8][kk + t + 4];
            }
            #pragma unroll
            for (int ni = 0; ni < 4; ni++) {
                int c = wn + ni * 8 + g;
                bf[ni][0] = Ks[c][kk + t];
                bf[ni][1] = Ks[c][kk + t + 4];
            }
            #pragma unroll
            for (int mi = 0; mi < 4; mi++)
                #pragma unroll
                for (int ni = 0; ni < 4; ni++)
                    mma_tf32(acc[mi][ni], a[mi][0], a[mi][1], a[mi][2], a[mi][3],
                             bf[ni][0], bf[ni][1]);
        }

        // E = exp(S/8), causal mask on diagonal tile; accumulate row sums
        const bool diag = (kt == qi);
        #pragma unroll
        for (int mi = 0; mi < 4; mi++) {
            int gr = wm + mi * 16 + g;
            #pragma unroll
            for (int ni = 0; ni < 4; ni++) {
                int gc = wn + ni * 8 + 2 * t;
                float e0 = __expf(acc[mi][ni][0] * 0.125f);
                float e1 = __expf(acc[mi][ni][1] * 0.125f);
                float e2 = __expf(acc[mi][ni][2] * 0.125f);
                float e3 = __expf(acc[mi][ni][3] * 0.125f);
                if (diag) {
                    if (gc > gr)         e0 = 0.f;
                    if (gc + 1 > gr)     e1 = 0.f;
                    if (gc > gr + 8)     e2 = 0.f;
                    if (gc + 1 > gr + 8) e3 = 0.f;
                }
                Es[gr][gc] = f2tf(e0);     Es[gr][gc + 1] = f2tf(e1);
                Es[gr + 8][gc] = f2tf(e2); Es[gr + 8][gc + 1] = f2tf(e3);
                sL[mi] += e0 + e1;
                sH[mi] += e2 + e3;
            }
        }
        __syncthreads();

        // AV += E V (128x64x128)
        #pragma unroll
        for (int kk = 0; kk < 128; kk += 8) {
            uint32_t a[2][4], bf[4][2];
            #pragma unroll
            for (int mi = 0; mi < 2; mi++) {
                int r = wm2 + mi * 16 + g;
                a[mi][0] = Es[r][kk + t];
                a[mi][1] = Es[r + 8][kk + t];
                a[mi][2] = Es[r][kk + t + 4];
                a[mi][3] = Es[r + 8][kk + t + 4];
            }
            #pragma unroll
            for (int ni = 0; ni < 4; ni++) {
                int c = wn2 + ni * 8 + g;
                bf[ni][0] = Vs[kk + t][c];
                bf[ni][1] = Vs[kk + t + 4][c];
            }
            #pragma unroll
            for (int mi = 0; mi < 2; mi++)
                #pragma unroll
                for (int ni = 0; ni < 4; ni++)
                    mma_tf32(av[mi][ni], a[mi][0], a[mi][1], a[mi][2], a[mi][3],
                             bf[ni][0], bf[ni][1]);
        }
    }

    // reduce row sums (4 n-warps share rows), publish inverses
    #pragma unroll
    for (int mi = 0; mi < 4; mi++) {
        float a = sL[mi], c = sH[mi];
        a += __shfl_xor_sync(0xffffffffu, a, 1);
        a += __shfl_xor_sync(0xffffffffu, a, 2);
        c += __shfl_xor_sync(0xffffffffu, c, 1);
        c += __shfl_xor_sync(0xffffffffu, c, 2);
        if (t == 0) {
            atomicAdd(&srow[wm + mi * 16 + g], a);
            atomicAdd(&srow[wm + mi * 16 + 8 + g], c);
        }
    }
    __syncthreads();
    if (tid < 128) {
        float inv = 1.0f / srow[tid];
        srow[tid] = inv;
        g_rowinv[(size_t)bh * S_ + q0 + tid] = inv;
    }
    __syncthreads();

    // epilogue: scale by 1/rowsum, write g_vals [B,S,E]
    #pragma unroll
    for (int mi = 0; mi < 2; mi++) {
        int r = wm2 + mi * 16 + g;
        float i0 = srow[r], i1 = srow[r + 8];
        #pragma unroll
        for (int ni = 0; ni < 4; ni++) {
            int d = h * HD_ + wn2 + ni * 8 + 2 * t;
            size_t o0 = ((size_t)b * S_ + q0 + r) * E_ + d;
            *(float2*)&g_vals[o0] =
                make_float2(av[mi][ni][0] * i0, av[mi][ni][1] * i0);
            *(float2*)&g_vals[o0 + (size_t)8 * E_] =
                make_float2(av[mi][ni][2] * i1, av[mi][ni][3] * i1);
        }
    }
}

// ---------------------------------------------------------------------------
// K3: attn writer. Recomputes QK^T per 128x128 tile and writes
// exp(s/8) * rowinv (zeros above diagonal); zero-fills upper tiles.
// Streaming stores (__stcs) — nothing re-reads attn.
// Dyn smem: Qs/Ks [128][68] = 69632 B.
// ---------------------------------------------------------------------------
__global__ __launch_bounds__(256) void attn_write_kernel(float* __restrict__ attn) {
    const int kt = blockIdx.x, qt = blockIdx.y, bh = blockIdx.z;
    const int tid = threadIdx.x;

    if (kt > qt) {  // strictly-upper tile: zeros
        const float4 z = make_float4(0.f, 0.f, 0.f, 0.f);
        #pragma unroll
        for (int i = 0; i < 16; i++) {
            int idx = tid + i * 256;
            int r = idx >> 5, c4 = (idx & 31) << 2;
            __stcs((float4*)&attn[((size_t)bh * S_ + qt * 128 + r) * S_ + kt * 128 + c4], z);
        }
        return;
    }

    const int b = bh >> 4, h = bh & 15;
    extern __shared__ uint32_t sm2[];
    uint32_t (*Qs)[68] = (uint32_t(*)[68])sm2;
    uint32_t (*Ks)[68] = (uint32_t(*)[68])(sm2 + 128 * 68);
    __shared__ float invs[128];

    const int warp = tid >> 5, lane = tid & 31;
    const int g = lane >> 2, t = lane & 3;
    const int wm = (warp >> 2) * 64, wn = (warp & 3) * 32;

    #pragma unroll
    for (int i = 0; i < 8; i++) {
        int idx = tid + i * 256;
        int r = idx >> 4, c4 = (idx & 15) << 2;
        float4 q = *(const float4*)&g_qkv[((size_t)b * S_ + qt * 128 + r) * N3E + h * 192 + c4];
        Qs[r][c4 + 0] = f2tf(q.x); Qs[r][c4 + 1] = f2tf(q.y);
        Qs[r][c4 + 2] = f2tf(q.z); Qs[r][c4 + 3] = f2tf(q.w);
        float4 k = *(const float4*)&g_qkv[((size_t)b * S_ + kt * 128 + r) * N3E + h * 192 + 64 + c4];
        Ks[r][c4 + 0] = f2tf(k.x); Ks[r][c4 + 1] = f2tf(k.y);
        Ks[r][c4 + 2] = f2tf(k.z); Ks[r][c4 + 3] = f2tf(k.w);
    }
    if (tid < 128) invs[tid] = g_rowinv[(size_t)bh * S_ + qt * 128 + tid];
    __syncthreads();

    float acc[4][4][4] = {};
    #pragma unroll
    for (int kk = 0; kk < 64; kk += 8) {
        uint32_t a[4][4], bf[4][2];
        #pragma unroll
        for (int mi = 0; mi < 4; mi++) {
            int r = wm + mi * 16 + g;
            a[mi][0] = Qs[r][kk + t];
            a[mi][1] = Qs[r + 8][kk + t];
            a[mi][2] = Qs[r][kk + t + 4];
            a[mi][3] = Qs[r + 8][kk + t + 4];
        }
        #pragma unroll
        for (int ni = 0; ni < 4; ni++) {
            int c = wn + ni * 8 + g;
            bf[ni][0] = Ks[c][kk + t];
            bf[ni][1] = Ks[c][kk + t + 4];
        }
        #pragma unroll
        for (int mi = 0; mi < 4; mi++)
            #pragma unroll
            for (int ni = 0; ni < 4; ni++)
                mma_tf32(acc[mi][ni], a[mi][0], a[mi][1], a[mi][2], a[mi][3],
                         bf[ni][0], bf[ni][1]);
    }

    const bool diag = (kt == qt);
    #pragma unroll
    for (int mi = 0; mi < 4; mi++) {
        int lr = wm + mi * 16 + g;
        int gr = qt * 128 + lr;
        float i0 = invs[lr], i1 = invs[lr + 8];
        #pragma unroll
        for (int ni = 0; ni < 4; ni++) {
            int lc = wn + ni * 8 + 2 * t;
            int gc = kt * 128 + lc;
            float e0 = __expf(acc[mi][ni][0] * 0.125f) * i0;
            float e1 = __expf(acc[mi][ni][1] * 0.125f) * i0;
            float e2 = __expf(acc[mi][ni][2] * 0.125f) * i1;
            float e3 = __expf(acc[mi][ni][3] * 0.125f) * i1;
            if (diag) {
                if (lc > lr)         e0 = 0.f;
                if (lc + 1 > lr)     e1 = 0.f;
                if (lc > lr + 8)     e2 = 0.f;
                if (lc + 1 > lr + 8) e3 = 0.f;
            }
            __stcs((float2*)&attn[((size_t)bh * S_ + gr) * S_ + gc],     make_float2(e0, e1));
            __stcs((float2*)&attn[((size_t)bh * S_ + gr + 8) * S_ + gc], make_float2(e2, e3));
        }
    }
}

// ---------------------------------------------------------------------------
extern "C" void kernel_launch(void* const* d_in, const int* in_sizes, int n_in,
                              void* d_out, int out_size) {
    const float* x     = (const float*)d_in[0];
    const float* w_qkv = (const float*)d_in[1];
    const float* b_qkv = (const float*)d_in[2];
    const float* w_o   = (const float*)d_in[3];
    const float* b_o   = (const float*)d_in[4];
    // d_in[5] = mask (causal, known analytically) — unused

    float* out  = (float*)d_out;
    float* attn = out + O_ELEMS;

    float* qkv_ptr = nullptr;
    float* vals_ptr = nullptr;
    cudaGetSymbolAddress((void**)&qkv_ptr, g_qkv);
    cudaGetSymbolAddress((void**)&vals_ptr, g_vals);

    cudaFuncSetAttribute(attn_fused_kernel,
                         cudaFuncAttributeMaxDynamicSharedMemorySize, 172032);
    cudaFuncSetAttribute(attn_write_kernel,
                         cudaFuncAttributeMaxDynamicSharedMemorySize, 69632);

    // 1) QKV projection [8192,1024]@[1024,3072]+b
    gemm_tf32_kernel<<<dim3(N3E / 128, MROWS / 128), 256>>>(
        x, w_qkv, b_qkv, qkv_ptr, MROWS, N3E, E_);

    // 2) fused attention: rowinv + A·V (no attn writes)
    attn_fused_kernel<<<dim3(16, 64), 256, 172032>>>();

    // 3) output projection [8192,1024]@[1024,1024]+b_o
    gemm_tf32_kernel<<<dim3(E_ / 128, MROWS / 128), 256>>>(
        vals_ptr, w_o, b_o, out, MROWS, E_, E_);

    // 4) attn writer: normalized probabilities (+ zeros), mandatory 1.07 GB
    attn_write_kernel<<<dim3(16, 16, 64), 256, 69632>>>(attn);
}